// round 6
// baseline (speedup 1.0000x reference)
#include <cuda_runtime.h>
#include <cuda_bf16.h>
#include <math.h>
#include <stdint.h>

#define NN 100000
#define EE 800000
#define HID 128
#define NH 4
#define DH 32
#define NBLK ((NN + 1023) / 1024)   // 98
#define NPAD 100096                 // node rows padded to tile multiple
#define NTILE_N 782                 // ceil(100000/128)
#define EPAD 68
#define TW (128 * EPAD)             // words per smem buffer (8704)
#define TB (TW * 4)                 // bytes per buffer (34816)
#define ESM_BYTES (6 * TB)          // Whi,Wlo + 2x(Ahi,Alo) = 208896 B

// ---------------- scratch (static device globals; no allocation) ----------------
__device__ unsigned int g_Ahi[(size_t)EE * 64];   // edge feats bf16-hi pairs [e][kw]
__device__ unsigned int g_Alo[(size_t)EE * 64];   // lo pairs
__device__ unsigned int g_hhi[(size_t)NPAD * 64]; // hidden bf16-hi pairs
__device__ unsigned int g_hlo[(size_t)NPAD * 64];
__device__ float g_xl[NN * HID];
__device__ float g_xr[NN * HID];
__device__ float g_h [NN * HID];
__device__ float g_score[EE * NH];
__device__ unsigned int g_WhiE[8192], g_WloE[8192];   // We^T images
__device__ unsigned int g_WhiL[8192], g_WloL[8192];   // Wl^T images
__device__ unsigned int g_WhiR[8192], g_WloR[8192];   // Wr^T images
__device__ int g_deg[NN], g_cursor[NN], g_rowptr[NN + 1], g_eids[EE];
__device__ int g_bsum[NBLK], g_boff[NBLK];

// ---------------- helpers ----------------
__device__ __forceinline__ float fast_silu(float z) {
    return __fdividef(z, 1.0f + __expf(-z));
}
__device__ __forceinline__ unsigned int packbf2(float x, float y) {
    __nv_bfloat162 t = __floats2bfloat162_rn(x, y);
    return *(unsigned int*)&t;
}
__device__ __forceinline__ void bf_split(float x, float& hi, float& lo) {
    __nv_bfloat16 h = __float2bfloat16_rn(x);
    hi = __bfloat162float(h);
    lo = x - hi;
}
__device__ __forceinline__ void mma_bf16(float c[4],
                                         unsigned int a0, unsigned int a1,
                                         unsigned int a2, unsigned int a3,
                                         unsigned int b0, unsigned int b1) {
    asm volatile("mma.sync.aligned.m16n8k16.row.col.f32.bf16.bf16.f32 "
                 "{%0,%1,%2,%3}, {%4,%5,%6,%7}, {%8,%9}, {%0,%1,%2,%3};"
                 : "+f"(c[0]), "+f"(c[1]), "+f"(c[2]), "+f"(c[3])
                 : "r"(a0), "r"(a1), "r"(a2), "r"(a3), "r"(b0), "r"(b1));
}
__device__ __forceinline__ uint32_t smem_u32(const void* p) {
    uint32_t a;
    asm("{ .reg .u64 t; cvta.to.shared.u64 t, %1; cvt.u32.u64 %0, t; }" : "=r"(a) : "l"(p));
    return a;
}
__device__ __forceinline__ void cp16(uint32_t d, const void* s) {
    size_t gs = __cvta_generic_to_global((void*)s);
    asm volatile("cp.async.cg.shared.global [%0], [%1], 16;"
                 :: "r"(d), "l"((unsigned long long)gs) : "memory");
}
__device__ __forceinline__ void cp_commit() {
    asm volatile("cp.async.commit_group;" ::: "memory");
}
template <int N>
__device__ __forceinline__ void cp_wait() {
    asm volatile("cp.async.wait_group %0;" :: "n"(N) : "memory");
}

// ---------------- edge feature projection: split bf16 hi/lo directly ------------
__global__ void eproj_kernel(const float* __restrict__ attr,
                             const float* __restrict__ W,
                             const float* __restrict__ b) {
    int idx = blockIdx.x * blockDim.x + threadIdx.x;   // E*32 threads
    int e = idx >> 5, c4 = (idx & 31) << 2;
    float a0 = __ldg(&attr[e * 3 + 0]);
    float a1 = __ldg(&attr[e * 3 + 1]);
    float a2 = __ldg(&attr[e * 3 + 2]);
    float v[4];
#pragma unroll
    for (int u = 0; u < 4; u++) {
        int j = c4 + u;
        float z = __ldg(&b[j]);
        z = fmaf(a0, __ldg(&W[j]),           z);
        z = fmaf(a1, __ldg(&W[HID + j]),     z);
        z = fmaf(a2, __ldg(&W[2 * HID + j]), z);
        v[u] = fast_silu(z);
    }
    float h0, l0, h1, l1, h2, l2, h3, l3;
    bf_split(v[0], h0, l0); bf_split(v[1], h1, l1);
    bf_split(v[2], h2, l2); bf_split(v[3], h3, l3);
    size_t base = (size_t)e * 64 + (c4 >> 1);
    *(uint2*)&g_Ahi[base] = make_uint2(packbf2(h0, h1), packbf2(h2, h3));
    *(uint2*)&g_Alo[base] = make_uint2(packbf2(l0, l1), packbf2(l2, l3));
}

// ---------------- CSR build (by dst) ----------------
__global__ void zero_kernel() {
    int i = blockIdx.x * blockDim.x + threadIdx.x;
    if (i < NN) { g_deg[i] = 0; g_cursor[i] = 0; }
}
__global__ void hist_kernel(const int* __restrict__ ei) {
    int e = blockIdx.x * blockDim.x + threadIdx.x;
    if (e < EE) atomicAdd(&g_deg[ei[EE + e]], 1);
}
__global__ void deg_block_sum() {
    __shared__ int sh[1024];
    int i = blockIdx.x * 1024 + threadIdx.x;
    sh[threadIdx.x] = (i < NN) ? g_deg[i] : 0;
    __syncthreads();
    for (int off = 512; off; off >>= 1) {
        if (threadIdx.x < off) sh[threadIdx.x] += sh[threadIdx.x + off];
        __syncthreads();
    }
    if (threadIdx.x == 0) g_bsum[blockIdx.x] = sh[0];
}
__global__ void bsum_scan() {
    __shared__ int sh[128];
    int t = threadIdx.x;
    int v = (t < NBLK) ? g_bsum[t] : 0;
    sh[t] = v;
    __syncthreads();
    for (int off = 1; off < 128; off <<= 1) {
        int u = (t >= off) ? sh[t - off] : 0;
        __syncthreads();
        sh[t] += u;
        __syncthreads();
    }
    if (t < NBLK) g_boff[t] = sh[t] - v;
}
__global__ void rowptr_kernel() {
    __shared__ int sh[1024];
    int i = blockIdx.x * 1024 + threadIdx.x;
    int v = (i < NN) ? g_deg[i] : 0;
    sh[threadIdx.x] = v;
    __syncthreads();
    for (int off = 1; off < 1024; off <<= 1) {
        int u = (threadIdx.x >= off) ? sh[threadIdx.x - off] : 0;
        __syncthreads();
        sh[threadIdx.x] += u;
        __syncthreads();
    }
    if (i < NN) g_rowptr[i + 1] = sh[threadIdx.x] + g_boff[blockIdx.x];
    if (i == 0) g_rowptr[0] = 0;
}
__global__ void scatter_kernel(const int* __restrict__ ei) {
    int e = blockIdx.x * blockDim.x + threadIdx.x;
    if (e < EE) {
        int d = ei[EE + e];
        int pos = atomicAdd(&g_cursor[d], 1);
        g_eids[g_rowptr[d] + pos] = e;
    }
}

// ---------------- W image prep: Wt[n][k] bf16 pairs, hi/lo split ----------------
// which: 0 -> edge (We), 1 -> Wl, 2 -> Wr
__global__ void wprep_kernel(const float* __restrict__ W, int which) {
    int idx = blockIdx.x * 256 + threadIdx.x;   // 8192
    int n = idx >> 6, kw = idx & 63;
    float w0 = __ldg(&W[(2 * kw) * HID + n]);
    float w1 = __ldg(&W[(2 * kw + 1) * HID + n]);
    float h0, l0, h1, l1;
    bf_split(w0, h0, l0);
    bf_split(w1, h1, l1);
    unsigned int* hi = (which == 0) ? g_WhiE : (which == 1) ? g_WhiL : g_WhiR;
    unsigned int* lo = (which == 0) ? g_WloE : (which == 1) ? g_WloL : g_WloR;
    hi[idx] = packbf2(h0, h1);
    lo[idx] = packbf2(l0, l1);
}

// ---------------- A tile prefetch via cp.async (hi/lo pair images) --------------
__device__ __forceinline__ void prefetch_A(uint32_t dhi, uint32_t dlo,
                                           const unsigned int* ghi,
                                           const unsigned int* glo,
                                           int m0, int tid) {
#pragma unroll
    for (int i = 0; i < 8; i++) {
        int idx = i * 256 + tid;
        int row = idx >> 4, c = (idx & 15) << 2;
        uint32_t doff = (uint32_t)(row * EPAD + c) * 4;
        cp16(dhi + doff, &ghi[(size_t)(m0 + row) * 64 + c]);
        cp16(dlo + doff, &glo[(size_t)(m0 + row) * 64 + c]);
    }
    cp_commit();
}

// ---------------- stage W images into smem (once per block) ---------------------
__device__ __forceinline__ void stage_W(unsigned int* esm,
                                        const unsigned int* ghi,
                                        const unsigned int* glo, int tid) {
#pragma unroll
    for (int i = 0; i < 8; i++) {
        int idx = i * 256 + tid, n = idx >> 4, c = (idx & 15) << 2;
        uint4 vh = ((const uint4*)ghi)[idx];
        uint4 vl = ((const uint4*)glo)[idx];
        *(uint4*)&esm[n * EPAD + c] = vh;
        *(uint4*)&esm[TW + n * EPAD + c] = vl;
    }
}

// ---------------- bf16x3 mma compute for one 128x128 tile ----------------------
__device__ __forceinline__ void tile_mma(float acc[2][8][4],
                                         const unsigned int* esm,
                                         const unsigned int* Ah,
                                         const unsigned int* Al,
                                         int mb, int nb, int g, int q) {
#pragma unroll
    for (int t = 0; t < 2; t++)
#pragma unroll
        for (int j = 0; j < 8; j++)
#pragma unroll
            for (int c = 0; c < 4; c++) acc[t][j][c] = 0.f;

    for (int pass = 0; pass < 3; pass++) {
        const unsigned int* As = (pass == 2) ? Al : Ah;
        const unsigned int* Bs = (pass == 1) ? esm + TW : esm;
#pragma unroll
        for (int ks = 0; ks < 8; ks++) {
            int kw0 = ks * 8 + q;
            unsigned int a[2][4];
#pragma unroll
            for (int t = 0; t < 2; t++) {
                int r = mb + 16 * t + g;
                a[t][0] = As[r * EPAD + kw0];
                a[t][1] = As[(r + 8) * EPAD + kw0];
                a[t][2] = As[r * EPAD + kw0 + 4];
                a[t][3] = As[(r + 8) * EPAD + kw0 + 4];
            }
            unsigned int b[8][2];
#pragma unroll
            for (int j = 0; j < 8; j++) {
                int n = nb + 8 * j + g;
                b[j][0] = Bs[n * EPAD + kw0];
                b[j][1] = Bs[n * EPAD + kw0 + 4];
            }
#pragma unroll
            for (int t = 0; t < 2; t++)
#pragma unroll
                for (int j = 0; j < 8; j++)
                    mma_bf16(acc[t][j], a[t][0], a[t][1], a[t][2], a[t][3],
                             b[j][0], b[j][1]);
        }
    }
}

// ================= pipelined edge GEMM + fused attention score ==================
__global__ __launch_bounds__(256, 1) void gemm_edge_score_mma(
        const float* __restrict__ att, const int* __restrict__ ei) {
    extern __shared__ __align__(16) unsigned int esm[];
    uint32_t sb = smem_u32(esm);
    int tid = threadIdx.x;
    int t0 = blockIdx.x * 5;

    stage_W(esm, g_WhiE, g_WloE, tid);
    prefetch_A(sb + 2 * TB, sb + 3 * TB, g_Ahi, g_Alo, t0 * 128, tid);

    int wid = tid >> 5, lane = tid & 31, g = lane >> 2, q = lane & 3;
    int mb = (wid & 3) * 32, nb = (wid >> 2) * 64;
    float2 attv[8];
#pragma unroll
    for (int j = 0; j < 8; j++)
        attv[j] = *(const float2*)&att[nb + 8 * j + 2 * q];

    for (int tt = 0; tt < 5; tt++) {
        int m0 = (t0 + tt) * 128;
        if (tt < 4) {
            uint32_t dhi = sb + (2 + 2 * ((tt + 1) & 1)) * TB;
            prefetch_A(dhi, dhi + TB, g_Ahi, g_Alo, (t0 + tt + 1) * 128, tid);
            cp_wait<1>();
        } else {
            cp_wait<0>();
        }
        __syncthreads();

        const unsigned int* Ah = esm + (2 + 2 * (tt & 1)) * TW;
        const unsigned int* Al = Ah + TW;
        float acc[2][8][4];
        tile_mma(acc, esm, Ah, Al, mb, nb, g, q);

        // fused epilogue: score[e][h] = sum_d leaky(ee + xl[src] + xr[dst]) * att
#pragma unroll
        for (int t = 0; t < 2; t++) {
#pragma unroll
            for (int rr = 0; rr < 2; rr++) {
                int row = mb + 16 * t + 8 * rr + g;
                int edge = m0 + row;
                int src = __ldg(&ei[edge]);
                int dst = __ldg(&ei[EE + edge]);
                const float* xlp = &g_xl[(size_t)src * HID];
                const float* xrp = &g_xr[(size_t)dst * HID];
                float p0 = 0.f, p1 = 0.f;
#pragma unroll
                for (int j = 0; j < 8; j++) {
                    int cc = nb + 8 * j + 2 * q;
                    float2 xl = *(const float2*)&xlp[cc];
                    float2 xr = *(const float2*)&xrp[cc];
                    float e0 = acc[t][j][rr * 2 + 0] + xl.x + xr.x;
                    float e1 = acc[t][j][rr * 2 + 1] + xl.y + xr.y;
                    e0 = (e0 > 0.f) ? e0 : 0.2f * e0;
                    e1 = (e1 > 0.f) ? e1 : 0.2f * e1;
                    float ps = fmaf(e0, attv[j].x, e1 * attv[j].y);
                    if (j < 4) p0 += ps; else p1 += ps;
                }
                p0 += __shfl_xor_sync(0xffffffffu, p0, 1);
                p0 += __shfl_xor_sync(0xffffffffu, p0, 2);
                p1 += __shfl_xor_sync(0xffffffffu, p1, 1);
                p1 += __shfl_xor_sync(0xffffffffu, p1, 2);
                if (q == 0)
                    *(float2*)&g_score[(size_t)edge * 4 + (nb >> 5)] =
                        make_float2(p0, p1);
            }
        }
        __syncthreads();
    }
}

// ================= pipelined node GEMM (xl / xr by blockIdx.y) ==================
__global__ __launch_bounds__(256, 1) void gemm_node_mma(
        const float* __restrict__ bl, const float* __restrict__ br) {
    extern __shared__ __align__(16) unsigned int esm[];
    uint32_t sb = smem_u32(esm);
    int tid = threadIdx.x;
    int t0 = blockIdx.x * 6;
    int nt = NTILE_N - t0;
    if (nt <= 0) return;
    if (nt > 6) nt = 6;

    const unsigned int* gWhi = blockIdx.y ? g_WhiR : g_WhiL;
    const unsigned int* gWlo = blockIdx.y ? g_WloR : g_WloL;
    float* C = blockIdx.y ? g_xr : g_xl;
    const float* bias = blockIdx.y ? br : bl;

    stage_W(esm, gWhi, gWlo, tid);
    prefetch_A(sb + 2 * TB, sb + 3 * TB, g_hhi, g_hlo, t0 * 128, tid);

    int wid = tid >> 5, lane = tid & 31, g = lane >> 2, q = lane & 3;
    int mb = (wid & 3) * 32, nb = (wid >> 2) * 64;
    float2 biasv[8];
#pragma unroll
    for (int j = 0; j < 8; j++)
        biasv[j] = *(const float2*)&bias[nb + 8 * j + 2 * q];

    for (int tt = 0; tt < nt; tt++) {
        int m0 = (t0 + tt) * 128;
        if (tt + 1 < nt) {
            uint32_t dhi = sb + (2 + 2 * ((tt + 1) & 1)) * TB;
            prefetch_A(dhi, dhi + TB, g_hhi, g_hlo, (t0 + tt + 1) * 128, tid);
            cp_wait<1>();
        } else {
            cp_wait<0>();
        }
        __syncthreads();

        const unsigned int* Ah = esm + (2 + 2 * (tt & 1)) * TW;
        const unsigned int* Al = Ah + TW;
        float acc[2][8][4];
        tile_mma(acc, esm, Ah, Al, mb, nb, g, q);

#pragma unroll
        for (int t = 0; t < 2; t++) {
#pragma unroll
            for (int rr = 0; rr < 2; rr++) {
                int row = mb + 16 * t + 8 * rr + g;
                int m = m0 + row;
                if (m < NN) {
#pragma unroll
                    for (int j = 0; j < 8; j++) {
                        int cc = nb + 8 * j + 2 * q;
                        *(float2*)&C[(size_t)m * HID + cc] =
                            make_float2(acc[t][j][rr * 2 + 0] + biasv[j].x,
                                        acc[t][j][rr * 2 + 1] + biasv[j].y);
                    }
                }
            }
        }
        __syncthreads();
    }
}

// ---------------- layer-0 node projection (K=12) ----------------
__global__ void node_proj12(const float* __restrict__ x,
                            const float* __restrict__ Wl, const float* __restrict__ bl,
                            const float* __restrict__ Wr, const float* __restrict__ br) {
    int idx = blockIdx.x * blockDim.x + threadIdx.x;
    int n = idx >> 7, j = idx & 127;
    float a = __ldg(&bl[j]);
    float b = __ldg(&br[j]);
#pragma unroll
    for (int k = 0; k < 12; k++) {
        float xv = __ldg(&x[n * 12 + k]);
        a = fmaf(xv, __ldg(&Wl[k * HID + j]), a);
        b = fmaf(xv, __ldg(&Wr[k * HID + j]), b);
    }
    g_xl[idx] = a;
    g_xr[idx] = b;
}

// ---------------- fused per-node: softmax + aggregate + bias + LN + SiLU (+res) ---
template <bool RES, bool LAST>
__global__ void node_fused_kernel(const int* __restrict__ ei,
                                  const float* __restrict__ gat_bias,
                                  const float* __restrict__ lng,
                                  const float* __restrict__ lnb,
                                  float* __restrict__ dout) {
    int n = blockIdx.x * 4 + (threadIdx.x >> 5);
    int lane = threadIdx.x & 31;
    if (n >= NN) return;
    int s0 = g_rowptr[n];
    int s1 = g_rowptr[n + 1];

    float mx = -3.4e38f;
    for (int p = s0 * 4 + lane; p < s1 * 4; p += 32) {
        int e = g_eids[p >> 2];
        mx = fmaxf(mx, g_score[(size_t)e * 4 + (p & 3)]);
    }
    mx = fmaxf(mx, __shfl_xor_sync(0xffffffffu, mx, 4));
    mx = fmaxf(mx, __shfl_xor_sync(0xffffffffu, mx, 8));
    mx = fmaxf(mx, __shfl_xor_sync(0xffffffffu, mx, 16));

    float den = 0.f;
    for (int p = s0 * 4 + lane; p < s1 * 4; p += 32) {
        int e = g_eids[p >> 2];
        den += __expf(g_score[(size_t)e * 4 + (p & 3)] - mx);
    }
    den += __shfl_xor_sync(0xffffffffu, den, 4);
    den += __shfl_xor_sync(0xffffffffu, den, 8);
    den += __shfl_xor_sync(0xffffffffu, den, 16);
    float inv = __fdividef(1.f, den + 1e-16f);

    float acc0 = 0.f, acc1 = 0.f, acc2 = 0.f, acc3 = 0.f;
    for (int i = s0; i < s1; i++) {
        int e = g_eids[i];
        int src = ei[e];
        float a = 0.f;
        if (lane < 4) a = __expf(g_score[(size_t)e * 4 + lane] - mx) * inv;
        float al0 = __shfl_sync(0xffffffffu, a, 0);
        float al1 = __shfl_sync(0xffffffffu, a, 1);
        float al2 = __shfl_sync(0xffffffffu, a, 2);
        float al3 = __shfl_sync(0xffffffffu, a, 3);
        const float* xl = &g_xl[(size_t)src * HID];
        acc0 = fmaf(xl[0 * DH + lane], al0, acc0);
        acc1 = fmaf(xl[1 * DH + lane], al1, acc1);
        acc2 = fmaf(xl[2 * DH + lane], al2, acc2);
        acc3 = fmaf(xl[3 * DH + lane], al3, acc3);
    }

    float v0 = acc0 + __ldg(&gat_bias[0 * DH + lane]);
    float v1 = acc1 + __ldg(&gat_bias[1 * DH + lane]);
    float v2 = acc2 + __ldg(&gat_bias[2 * DH + lane]);
    float v3 = acc3 + __ldg(&gat_bias[3 * DH + lane]);

    float sm = v0 + v1 + v2 + v3;
#pragma unroll
    for (int off = 16; off; off >>= 1) sm += __shfl_xor_sync(0xffffffffu, sm, off);
    float mean = sm * (1.f / 128.f);
    float d0 = v0 - mean, d1 = v1 - mean, d2 = v2 - mean, d3 = v3 - mean;
    float sq = d0 * d0 + d1 * d1 + d2 * d2 + d3 * d3;
#pragma unroll
    for (int off = 16; off; off >>= 1) sq += __shfl_xor_sync(0xffffffffu, sq, off);
    float rstd = rsqrtf(sq * (1.f / 128.f) + 1e-5f);

#pragma unroll
    for (int h = 0; h < 4; h++) {
        int j = h * DH + lane;
        float d = (h == 0 ? d0 : h == 1 ? d1 : h == 2 ? d2 : d3);
        float t = fmaf(d * rstd, __ldg(&lng[j]), __ldg(&lnb[j]));
        float sil = fast_silu(t);
        float o = RES ? (g_h[n * HID + j] + sil) : sil;
        if (LAST) {
            dout[n * HID + j] = o;
        } else {
            g_h[n * HID + j] = o;
            // bf16 split pairs for next layer's node GEMM
            float on = __shfl_down_sync(0xffffffffu, o, 1);
            if (!(lane & 1)) {
                float h0, l0, h1, l1;
                bf_split(o, h0, l0);
                bf_split(on, h1, l1);
                g_hhi[(size_t)n * 64 + (j >> 1)] = packbf2(h0, h1);
                g_hlo[(size_t)n * 64 + (j >> 1)] = packbf2(l0, l1);
            }
        }
    }
}

// ---------------- launch ----------------
extern "C" void kernel_launch(void* const* d_in, const int* in_sizes, int n_in,
                              void* d_out, int out_size) {
    const float* x     = (const float*)d_in[0];
    const int*   ei    = (const int*)  d_in[1];
    const float* eattr = (const float*)d_in[2];
    const float* epw   = (const float*)d_in[3];
    const float* epb   = (const float*)d_in[4];
    const float* l0Wl  = (const float*)d_in[5];
    const float* l0bl  = (const float*)d_in[6];
    const float* l0Wr  = (const float*)d_in[7];
    const float* l0br  = (const float*)d_in[8];
    const float* l0We  = (const float*)d_in[9];
    const float* l0att = (const float*)d_in[10];
    const float* l0bias= (const float*)d_in[11];
    const float* Wl    = (const float*)d_in[12];
    const float* bl    = (const float*)d_in[13];
    const float* Wr    = (const float*)d_in[14];
    const float* br    = (const float*)d_in[15];
    const float* We    = (const float*)d_in[16];
    const float* att   = (const float*)d_in[17];
    const float* bias  = (const float*)d_in[18];
    const float* lng   = (const float*)d_in[19];
    const float* lnb   = (const float*)d_in[20];
    float* out = (float*)d_out;

    static bool attr_set = false;
    if (!attr_set) {
        cudaFuncSetAttribute(gemm_edge_score_mma,
                             cudaFuncAttributeMaxDynamicSharedMemorySize, ESM_BYTES);
        cudaFuncSetAttribute(gemm_node_mma,
                             cudaFuncAttributeMaxDynamicSharedMemorySize, ESM_BYTES);
        attr_set = true;
    }

    // layer-0 prerequisites; edge GEMM kept at 4th launch for ncu capture
    eproj_kernel<<<(EE * 32) / 256, 256>>>(eattr, epw, epb);
    node_proj12<<<(NN * HID) / 256, 256>>>(x, l0Wl, l0bl, l0Wr, l0br);
    wprep_kernel<<<32, 256>>>(l0We, 0);
    gemm_edge_score_mma<<<1250, 256, ESM_BYTES>>>(l0att, ei);

    // CSR build
    zero_kernel<<<(NN + 255) / 256, 256>>>();
    hist_kernel<<<(EE + 255) / 256, 256>>>(ei);
    deg_block_sum<<<NBLK, 1024>>>();
    bsum_scan<<<1, 128>>>();
    rowptr_kernel<<<NBLK, 1024>>>();
    scatter_kernel<<<(EE + 255) / 256, 256>>>(ei);

    node_fused_kernel<false, false><<<NN / 4, 128>>>(ei, l0bias, lng, lnb, nullptr);

    // layers 1..3 (residual)
    for (int i = 0; i < 3; i++) {
        wprep_kernel<<<32, 256>>>(Wl + i * HID * HID, 1);
        wprep_kernel<<<32, 256>>>(Wr + i * HID * HID, 2);
        wprep_kernel<<<32, 256>>>(We + i * HID * HID, 0);
        dim3 ng((NTILE_N + 5) / 6, 2);
        gemm_node_mma<<<ng, 256, ESM_BYTES>>>(bl + i * HID, br + i * HID);
        gemm_edge_score_mma<<<1250, 256, ESM_BYTES>>>(att + i * HID, ei);
        if (i < 2)
            node_fused_kernel<true, false><<<NN / 4, 128>>>(
                ei, bias + i * HID, lng + (i + 1) * HID, lnb + (i + 1) * HID, nullptr);
        else
            node_fused_kernel<true, true><<<NN / 4, 128>>>(
                ei, bias + i * HID, lng + (i + 1) * HID, lnb + (i + 1) * HID, out);
    }
}

// round 7
// speedup vs baseline: 1.2988x; 1.2988x over previous
#include <cuda_runtime.h>
#include <cuda_bf16.h>
#include <math.h>
#include <stdint.h>

#define NN 100000
#define EE 800000
#define HID 128
#define NH 4
#define DH 32
#define NBLK ((NN + 1023) / 1024)   // 98
#define EPAD 68
#define TW (128 * EPAD)             // words per smem image (8704)
#define TB (TW * 4)                 // bytes per image (34816)
#define ESM_BYTES (4 * TB)          // Whi, Wlo, Ahi, Alo = 139264 B

// ---------------- scratch (static device globals; no allocation) ----------------
__device__ unsigned int g_Ahi[(size_t)EE * 64];   // edge feats bf16-hi pairs [e][kw]
__device__ unsigned int g_Alo[(size_t)EE * 64];   // lo pairs
__device__ float g_xl[NN * HID];
__device__ float g_xr[NN * HID];
__device__ float g_h [NN * HID];
__device__ float g_score[EE * NH];
__device__ unsigned int g_WhiE[8192], g_WloE[8192];   // We^T bf16-pair images
__device__ int g_deg[NN], g_cursor[NN], g_rowptr[NN + 1], g_eids[EE];
__device__ int g_bsum[NBLK], g_boff[NBLK];

// ---------------- helpers ----------------
__device__ __forceinline__ float fast_silu(float z) {
    return __fdividef(z, 1.0f + __expf(-z));
}
__device__ __forceinline__ unsigned int packbf2(float x, float y) {
    __nv_bfloat162 t = __floats2bfloat162_rn(x, y);
    return *(unsigned int*)&t;
}
__device__ __forceinline__ void bf_split(float x, float& hi, float& lo) {
    __nv_bfloat16 h = __float2bfloat16_rn(x);
    hi = __bfloat162float(h);
    lo = x - hi;
}
__device__ __forceinline__ void mma_bf16(float c[4],
                                         unsigned int a0, unsigned int a1,
                                         unsigned int a2, unsigned int a3,
                                         unsigned int b0, unsigned int b1) {
    asm volatile("mma.sync.aligned.m16n8k16.row.col.f32.bf16.bf16.f32 "
                 "{%0,%1,%2,%3}, {%4,%5,%6,%7}, {%8,%9}, {%0,%1,%2,%3};"
                 : "+f"(c[0]), "+f"(c[1]), "+f"(c[2]), "+f"(c[3])
                 : "r"(a0), "r"(a1), "r"(a2), "r"(a3), "r"(b0), "r"(b1));
}
// packed fp32x2 (FFMA2) for the node GEMM
__device__ __forceinline__ unsigned long long pack2(float x, float y) {
    unsigned long long r;
    asm("mov.b64 %0, {%1, %2};" : "=l"(r) : "f"(x), "f"(y));
    return r;
}
__device__ __forceinline__ unsigned long long bcast2(float x) {
    unsigned long long r;
    asm("mov.b64 %0, {%1, %1};" : "=l"(r) : "f"(x));
    return r;
}
__device__ __forceinline__ void ffma2(unsigned long long& d,
                                      unsigned long long a, unsigned long long b) {
    asm("fma.rn.f32x2 %0, %1, %2, %0;" : "+l"(d) : "l"(a), "l"(b));
}
__device__ __forceinline__ uint32_t smem_u32(const void* p) {
    uint32_t a;
    asm("{ .reg .u64 t; cvta.to.shared.u64 t, %1; cvt.u32.u64 %0, t; }" : "=r"(a) : "l"(p));
    return a;
}
__device__ __forceinline__ void cp16(uint32_t d, const void* s) {
    size_t gs = __cvta_generic_to_global((void*)s);
    asm volatile("cp.async.cg.shared.global [%0], [%1], 16;"
                 :: "r"(d), "l"((unsigned long long)gs) : "memory");
}
__device__ __forceinline__ void cp_commit() {
    asm volatile("cp.async.commit_group;" ::: "memory");
}
template <int N>
__device__ __forceinline__ void cp_wait() {
    asm volatile("cp.async.wait_group %0;" :: "n"(N) : "memory");
}

// ---------------- edge feature projection: bf16 hi/lo pair images ----------------
__global__ void eproj_kernel(const float* __restrict__ attr,
                             const float* __restrict__ W,
                             const float* __restrict__ b) {
    int idx = blockIdx.x * blockDim.x + threadIdx.x;   // E*32 threads
    int e = idx >> 5, c4 = (idx & 31) << 2;
    float a0 = __ldg(&attr[e * 3 + 0]);
    float a1 = __ldg(&attr[e * 3 + 1]);
    float a2 = __ldg(&attr[e * 3 + 2]);
    float v[4];
#pragma unroll
    for (int u = 0; u < 4; u++) {
        int j = c4 + u;
        float z = __ldg(&b[j]);
        z = fmaf(a0, __ldg(&W[j]),           z);
        z = fmaf(a1, __ldg(&W[HID + j]),     z);
        z = fmaf(a2, __ldg(&W[2 * HID + j]), z);
        v[u] = fast_silu(z);
    }
    float h0, l0, h1, l1, h2, l2, h3, l3;
    bf_split(v[0], h0, l0); bf_split(v[1], h1, l1);
    bf_split(v[2], h2, l2); bf_split(v[3], h3, l3);
    size_t base = (size_t)e * 64 + (c4 >> 1);
    *(uint2*)&g_Ahi[base] = make_uint2(packbf2(h0, h1), packbf2(h2, h3));
    *(uint2*)&g_Alo[base] = make_uint2(packbf2(l0, l1), packbf2(l2, l3));
}

// ---------------- CSR build (by dst) ----------------
__global__ void zero_kernel() {
    int i = blockIdx.x * blockDim.x + threadIdx.x;
    if (i < NN) { g_deg[i] = 0; g_cursor[i] = 0; }
}
__global__ void hist_kernel(const int* __restrict__ ei) {
    int e = blockIdx.x * blockDim.x + threadIdx.x;
    if (e < EE) atomicAdd(&g_deg[ei[EE + e]], 1);
}
__global__ void deg_block_sum() {
    __shared__ int sh[1024];
    int i = blockIdx.x * 1024 + threadIdx.x;
    sh[threadIdx.x] = (i < NN) ? g_deg[i] : 0;
    __syncthreads();
    for (int off = 512; off; off >>= 1) {
        if (threadIdx.x < off) sh[threadIdx.x] += sh[threadIdx.x + off];
        __syncthreads();
    }
    if (threadIdx.x == 0) g_bsum[blockIdx.x] = sh[0];
}
__global__ void bsum_scan() {
    __shared__ int sh[128];
    int t = threadIdx.x;
    int v = (t < NBLK) ? g_bsum[t] : 0;
    sh[t] = v;
    __syncthreads();
    for (int off = 1; off < 128; off <<= 1) {
        int u = (t >= off) ? sh[t - off] : 0;
        __syncthreads();
        sh[t] += u;
        __syncthreads();
    }
    if (t < NBLK) g_boff[t] = sh[t] - v;
}
__global__ void rowptr_kernel() {
    __shared__ int sh[1024];
    int i = blockIdx.x * 1024 + threadIdx.x;
    int v = (i < NN) ? g_deg[i] : 0;
    sh[threadIdx.x] = v;
    __syncthreads();
    for (int off = 1; off < 1024; off <<= 1) {
        int u = (threadIdx.x >= off) ? sh[threadIdx.x - off] : 0;
        __syncthreads();
        sh[threadIdx.x] += u;
        __syncthreads();
    }
    if (i < NN) g_rowptr[i + 1] = sh[threadIdx.x] + g_boff[blockIdx.x];
    if (i == 0) g_rowptr[0] = 0;
}
__global__ void scatter_kernel(const int* __restrict__ ei) {
    int e = blockIdx.x * blockDim.x + threadIdx.x;
    if (e < EE) {
        int d = ei[EE + e];
        int pos = atomicAdd(&g_cursor[d], 1);
        g_eids[g_rowptr[d] + pos] = e;
    }
}

// ---------------- W image prep (edge We only) ----------------
__global__ void wprep_kernel(const float* __restrict__ W) {
    int idx = blockIdx.x * 256 + threadIdx.x;   // 8192
    int n = idx >> 6, kw = idx & 63;
    float w0 = __ldg(&W[(2 * kw) * HID + n]);
    float w1 = __ldg(&W[(2 * kw + 1) * HID + n]);
    float h0, l0, h1, l1;
    bf_split(w0, h0, l0);
    bf_split(w1, h1, l1);
    g_WhiE[idx] = packbf2(h0, h1);
    g_WloE[idx] = packbf2(l0, l1);
}

// ================= edge GEMM (bf16x3 mma, 512 threads, 32x32 warp tiles) ========
__global__ __launch_bounds__(512, 1) void gemm_edge_score_mma(
        const float* __restrict__ att, const int* __restrict__ ei) {
    extern __shared__ __align__(16) unsigned int esm[];
    // layout: Whi[TW] | Wlo[TW] | Ahi[TW] | Alo[TW]
    uint32_t sb = smem_u32(esm);
    int tid = threadIdx.x;
    int m0 = blockIdx.x * 128;

    // stage A via cp.async (pure copies, pre-split images)
#pragma unroll
    for (int i = 0; i < 4; i++) {
        int idx = i * 512 + tid;
        int row = idx >> 4, c = (idx & 15) << 2;
        uint32_t doff = (uint32_t)(row * EPAD + c) * 4;
        cp16(sb + 2 * TB + doff, &g_Ahi[(size_t)(m0 + row) * 64 + c]);
        cp16(sb + 3 * TB + doff, &g_Alo[(size_t)(m0 + row) * 64 + c]);
    }
    cp_commit();

    // stage W (regular uint4 loads; overlaps with cp.async above)
#pragma unroll
    for (int i = 0; i < 4; i++) {
        int idx = i * 512 + tid;
        int n = idx >> 4, c = (idx & 15) << 2;
        uint4 vh = ((const uint4*)g_WhiE)[idx];
        uint4 vl = ((const uint4*)g_WloE)[idx];
        *(uint4*)&esm[n * EPAD + c] = vh;
        *(uint4*)&esm[TW + n * EPAD + c] = vl;
    }
    cp_wait<0>();
    __syncthreads();

    int wid = tid >> 5, lane = tid & 31, g = lane >> 2, q = lane & 3;
    int mb = (wid & 3) * 32;        // rows mb..mb+31
    int nb = (wid >> 2) * 32;       // cols nb..nb+31 (one head)

    float acc[2][4][4];
#pragma unroll
    for (int t = 0; t < 2; t++)
#pragma unroll
        for (int j = 0; j < 4; j++)
#pragma unroll
            for (int c = 0; c < 4; c++) acc[t][j][c] = 0.f;

    // 3 passes: (Ahi,Whi), (Ahi,Wlo), (Alo,Whi)
    for (int pass = 0; pass < 3; pass++) {
        const unsigned int* As = (pass == 2) ? esm + 3 * TW : esm + 2 * TW;
        const unsigned int* Bs = (pass == 1) ? esm + TW : esm;
#pragma unroll
        for (int ks = 0; ks < 8; ks++) {
            int kw0 = ks * 8 + q;
            unsigned int a[2][4];
#pragma unroll
            for (int t = 0; t < 2; t++) {
                int r = mb + 16 * t + g;
                a[t][0] = As[r * EPAD + kw0];
                a[t][1] = As[(r + 8) * EPAD + kw0];
                a[t][2] = As[r * EPAD + kw0 + 4];
                a[t][3] = As[(r + 8) * EPAD + kw0 + 4];
            }
            unsigned int b[4][2];
#pragma unroll
            for (int j = 0; j < 4; j++) {
                int n = nb + 8 * j + g;
                b[j][0] = Bs[n * EPAD + kw0];
                b[j][1] = Bs[n * EPAD + kw0 + 4];
            }
#pragma unroll
            for (int t = 0; t < 2; t++)
#pragma unroll
                for (int j = 0; j < 4; j++)
                    mma_bf16(acc[t][j], a[t][0], a[t][1], a[t][2], a[t][3],
                             b[j][0], b[j][1]);
        }
    }

    // fused epilogue: score[e][head] = sum_d leaky(ee + xl[src] + xr[dst]) * att
    float2 attv[4];
#pragma unroll
    for (int j = 0; j < 4; j++)
        attv[j] = *(const float2*)&att[nb + 8 * j + 2 * q];

#pragma unroll
    for (int t = 0; t < 2; t++) {
#pragma unroll
        for (int rr = 0; rr < 2; rr++) {
            int row = mb + 16 * t + 8 * rr + g;
            int edge = m0 + row;
            int src = __ldg(&ei[edge]);
            int dst = __ldg(&ei[EE + edge]);
            const float* xlp = &g_xl[(size_t)src * HID];
            const float* xrp = &g_xr[(size_t)dst * HID];
            float p = 0.f;
#pragma unroll
            for (int j = 0; j < 4; j++) {
                int cc = nb + 8 * j + 2 * q;
                float2 xl = *(const float2*)&xlp[cc];
                float2 xr = *(const float2*)&xrp[cc];
                float e0 = acc[t][j][rr * 2 + 0] + xl.x + xr.x;
                float e1 = acc[t][j][rr * 2 + 1] + xl.y + xr.y;
                e0 = (e0 > 0.f) ? e0 : 0.2f * e0;
                e1 = (e1 > 0.f) ? e1 : 0.2f * e1;
                p += fmaf(e0, attv[j].x, e1 * attv[j].y);
            }
            p += __shfl_xor_sync(0xffffffffu, p, 1);
            p += __shfl_xor_sync(0xffffffffu, p, 2);
            if (q == 0)
                g_score[(size_t)edge * 4 + (nb >> 5)] = p;
        }
    }
}

// ================= SIMT node GEMM (proven FFMA2 path, round-5) ==================
#define WS_FLOATS (HID * HID)
#define AS_PAD 132
#define AS_FLOATS (32 * AS_PAD)

__device__ __forceinline__ void load_W_smem(float* Wsm, const float* __restrict__ W, int tid) {
    const float4* Wv = (const float4*)W;
    float4* Wd = (float4*)Wsm;
#pragma unroll
    for (int i = 0; i < WS_FLOATS / 4 / 256; i++)
        Wd[tid + 256 * i] = Wv[tid + 256 * i];
}
__device__ __forceinline__ void loadA_regs(float4 pa[4], const float* __restrict__ A,
                                           int m0, int k0, int lr, int lc) {
#pragma unroll
    for (int i = 0; i < 4; i++) {
        int m = m0 + lr + 32 * i;
        if (m < NN)
            pa[i] = *(const float4*)&A[(size_t)m * HID + k0 + lc];
        else
            pa[i] = make_float4(0.f, 0.f, 0.f, 0.f);
    }
}
__device__ __forceinline__ void storeA_smem(float* As, const float4 pa[4], int lr, int lc) {
#pragma unroll
    for (int i = 0; i < 4; i++) {
        As[(lc + 0) * AS_PAD + lr + 32 * i] = pa[i].x;
        As[(lc + 1) * AS_PAD + lr + 32 * i] = pa[i].y;
        As[(lc + 2) * AS_PAD + lr + 32 * i] = pa[i].z;
        As[(lc + 3) * AS_PAD + lr + 32 * i] = pa[i].w;
    }
}
__device__ __forceinline__ void compute_chunk(unsigned long long acc2[8][4],
                                              const float* As, const float* Wsm,
                                              int k0, int tx, int ty) {
#pragma unroll 8
    for (int kk = 0; kk < 32; kk++) {
        float4 a0 = *(const float4*)&As[kk * AS_PAD + ty * 8];
        float4 a1 = *(const float4*)&As[kk * AS_PAD + ty * 8 + 4];
        float4 b0 = *(const float4*)&Wsm[(k0 + kk) * HID + tx * 8];
        float4 b1 = *(const float4*)&Wsm[(k0 + kk) * HID + tx * 8 + 4];
        unsigned long long bp[4] = {pack2(b0.x, b0.y), pack2(b0.z, b0.w),
                                    pack2(b1.x, b1.y), pack2(b1.z, b1.w)};
        float a[8] = {a0.x, a0.y, a0.z, a0.w, a1.x, a1.y, a1.z, a1.w};
#pragma unroll
        for (int i = 0; i < 8; i++) {
            unsigned long long ap = bcast2(a[i]);
#pragma unroll
            for (int j = 0; j < 4; j++) ffma2(acc2[i][j], ap, bp[j]);
        }
    }
}

__global__ __launch_bounds__(256, 2) void gemm_node(const float* __restrict__ Wl,
                                                    const float* __restrict__ bl,
                                                    const float* __restrict__ Wr,
                                                    const float* __restrict__ br) {
    extern __shared__ __align__(16) float smem[];
    float* Wsm = smem;
    float* As = smem + WS_FLOATS;

    const float* W    = blockIdx.y ? Wr : Wl;
    const float* bias = blockIdx.y ? br : bl;
    float* C          = blockIdx.y ? g_xr : g_xl;
    const float* A = g_h;

    int tid = threadIdx.x;
    int tx = tid & 15, ty = tid >> 4;
    int lr = tid >> 3, lc = (tid & 7) << 2;
    int m0 = blockIdx.x * 128;

    load_W_smem(Wsm, W, tid);

    unsigned long long acc2[8][4];
#pragma unroll
    for (int i = 0; i < 8; i++)
#pragma unroll
        for (int j = 0; j < 4; j++) acc2[i][j] = 0ull;

    float4 pa[4];
    loadA_regs(pa, A, m0, 0, lr, lc);
    storeA_smem(As, pa, lr, lc);
    __syncthreads();

#pragma unroll
    for (int c = 0; c < 4; c++) {
        if (c < 3) loadA_regs(pa, A, m0, (c + 1) * 32, lr, lc);
        compute_chunk(acc2, As, Wsm, c * 32, tx, ty);
        __syncthreads();
        if (c < 3) { storeA_smem(As, pa, lr, lc); __syncthreads(); }
    }

#pragma unroll
    for (int i = 0; i < 8; i++) {
        int m = m0 + ty * 8 + i;
        if (m < NN) {
#pragma unroll
            for (int jp = 0; jp < 4; jp += 2) {
                float2 p0 = *(float2*)&acc2[i][jp];
                float2 p1 = *(float2*)&acc2[i][jp + 1];
                int ccol = tx * 8 + jp * 2;
                float4 o;
                o.x = p0.x + __ldg(&bias[ccol + 0]);
                o.y = p0.y + __ldg(&bias[ccol + 1]);
                o.z = p1.x + __ldg(&bias[ccol + 2]);
                o.w = p1.y + __ldg(&bias[ccol + 3]);
                *(float4*)&C[(size_t)m * HID + ccol] = o;
            }
        }
    }
}

// ---------------- layer-0 node projection (K=12) ----------------
__global__ void node_proj12(const float* __restrict__ x,
                            const float* __restrict__ Wl, const float* __restrict__ bl,
                            const float* __restrict__ Wr, const float* __restrict__ br) {
    int idx = blockIdx.x * blockDim.x + threadIdx.x;
    int n = idx >> 7, j = idx & 127;
    float a = __ldg(&bl[j]);
    float b = __ldg(&br[j]);
#pragma unroll
    for (int k = 0; k < 12; k++) {
        float xv = __ldg(&x[n * 12 + k]);
        a = fmaf(xv, __ldg(&Wl[k * HID + j]), a);
        b = fmaf(xv, __ldg(&Wr[k * HID + j]), b);
    }
    g_xl[idx] = a;
    g_xr[idx] = b;
}

// ---------------- fused per-node: softmax + aggregate + bias + LN + SiLU (+res) ---
template <bool RES, bool LAST>
__global__ void node_fused_kernel(const int* __restrict__ ei,
                                  const float* __restrict__ gat_bias,
                                  const float* __restrict__ lng,
                                  const float* __restrict__ lnb,
                                  float* __restrict__ dout) {
    int n = blockIdx.x * 4 + (threadIdx.x >> 5);
    int lane = threadIdx.x & 31;
    if (n >= NN) return;
    int s0 = g_rowptr[n];
    int s1 = g_rowptr[n + 1];

    float mx = -3.4e38f;
    for (int p = s0 * 4 + lane; p < s1 * 4; p += 32) {
        int e = g_eids[p >> 2];
        mx = fmaxf(mx, g_score[(size_t)e * 4 + (p & 3)]);
    }
    mx = fmaxf(mx, __shfl_xor_sync(0xffffffffu, mx, 4));
    mx = fmaxf(mx, __shfl_xor_sync(0xffffffffu, mx, 8));
    mx = fmaxf(mx, __shfl_xor_sync(0xffffffffu, mx, 16));

    float den = 0.f;
    for (int p = s0 * 4 + lane; p < s1 * 4; p += 32) {
        int e = g_eids[p >> 2];
        den += __expf(g_score[(size_t)e * 4 + (p & 3)] - mx);
    }
    den += __shfl_xor_sync(0xffffffffu, den, 4);
    den += __shfl_xor_sync(0xffffffffu, den, 8);
    den += __shfl_xor_sync(0xffffffffu, den, 16);
    float inv = __fdividef(1.f, den + 1e-16f);

    float acc0 = 0.f, acc1 = 0.f, acc2 = 0.f, acc3 = 0.f;
    for (int i = s0; i < s1; i++) {
        int e = g_eids[i];
        int src = ei[e];
        float a = 0.f;
        if (lane < 4) a = __expf(g_score[(size_t)e * 4 + lane] - mx) * inv;
        float al0 = __shfl_sync(0xffffffffu, a, 0);
        float al1 = __shfl_sync(0xffffffffu, a, 1);
        float al2 = __shfl_sync(0xffffffffu, a, 2);
        float al3 = __shfl_sync(0xffffffffu, a, 3);
        const float* xl = &g_xl[(size_t)src * HID];
        acc0 = fmaf(xl[0 * DH + lane], al0, acc0);
        acc1 = fmaf(xl[1 * DH + lane], al1, acc1);
        acc2 = fmaf(xl[2 * DH + lane], al2, acc2);
        acc3 = fmaf(xl[3 * DH + lane], al3, acc3);
    }

    float v0 = acc0 + __ldg(&gat_bias[0 * DH + lane]);
    float v1 = acc1 + __ldg(&gat_bias[1 * DH + lane]);
    float v2 = acc2 + __ldg(&gat_bias[2 * DH + lane]);
    float v3 = acc3 + __ldg(&gat_bias[3 * DH + lane]);

    float sm = v0 + v1 + v2 + v3;
#pragma unroll
    for (int off = 16; off; off >>= 1) sm += __shfl_xor_sync(0xffffffffu, sm, off);
    float mean = sm * (1.f / 128.f);
    float d0 = v0 - mean, d1 = v1 - mean, d2 = v2 - mean, d3 = v3 - mean;
    float sq = d0 * d0 + d1 * d1 + d2 * d2 + d3 * d3;
#pragma unroll
    for (int off = 16; off; off >>= 1) sq += __shfl_xor_sync(0xffffffffu, sq, off);
    float rstd = rsqrtf(sq * (1.f / 128.f) + 1e-5f);

#pragma unroll
    for (int h = 0; h < 4; h++) {
        int j = h * DH + lane;
        float d = (h == 0 ? d0 : h == 1 ? d1 : h == 2 ? d2 : d3);
        float t = fmaf(d * rstd, __ldg(&lng[j]), __ldg(&lnb[j]));
        float sil = fast_silu(t);
        float o = RES ? (g_h[n * HID + j] + sil) : sil;
        if (LAST) dout[n * HID + j] = o;
        else      g_h[n * HID + j] = o;
    }
}

// ---------------- launch ----------------
extern "C" void kernel_launch(void* const* d_in, const int* in_sizes, int n_in,
                              void* d_out, int out_size) {
    const float* x     = (const float*)d_in[0];
    const int*   ei    = (const int*)  d_in[1];
    const float* eattr = (const float*)d_in[2];
    const float* epw   = (const float*)d_in[3];
    const float* epb   = (const float*)d_in[4];
    const float* l0Wl  = (const float*)d_in[5];
    const float* l0bl  = (const float*)d_in[6];
    const float* l0Wr  = (const float*)d_in[7];
    const float* l0br  = (const float*)d_in[8];
    const float* l0We  = (const float*)d_in[9];
    const float* l0att = (const float*)d_in[10];
    const float* l0bias= (const float*)d_in[11];
    const float* Wl    = (const float*)d_in[12];
    const float* bl    = (const float*)d_in[13];
    const float* Wr    = (const float*)d_in[14];
    const float* br    = (const float*)d_in[15];
    const float* We    = (const float*)d_in[16];
    const float* att   = (const float*)d_in[17];
    const float* bias  = (const float*)d_in[18];
    const float* lng   = (const float*)d_in[19];
    const float* lnb   = (const float*)d_in[20];
    float* out = (float*)d_out;

    const int NODE_SMEM = (WS_FLOATS + AS_FLOATS) * 4;
    static bool attr_set = false;
    if (!attr_set) {
        cudaFuncSetAttribute(gemm_edge_score_mma,
                             cudaFuncAttributeMaxDynamicSharedMemorySize, ESM_BYTES);
        cudaFuncSetAttribute(gemm_node,
                             cudaFuncAttributeMaxDynamicSharedMemorySize, NODE_SMEM);
        attr_set = true;
    }

    // layer-0 prerequisites; edge GEMM kept at 4th launch for ncu capture
    eproj_kernel<<<(EE * 32) / 256, 256>>>(eattr, epw, epb);
    node_proj12<<<(NN * HID) / 256, 256>>>(x, l0Wl, l0bl, l0Wr, l0br);
    wprep_kernel<<<32, 256>>>(l0We);
    gemm_edge_score_mma<<<EE / 128, 512, ESM_BYTES>>>(l0att, ei);

    // CSR build
    zero_kernel<<<(NN + 255) / 256, 256>>>();
    hist_kernel<<<(EE + 255) / 256, 256>>>(ei);
    deg_block_sum<<<NBLK, 1024>>>();
    bsum_scan<<<1, 128>>>();
    rowptr_kernel<<<NBLK, 1024>>>();
    scatter_kernel<<<(EE + 255) / 256, 256>>>(ei);

    node_fused_kernel<false, false><<<NN / 4, 128>>>(ei, l0bias, lng, lnb, nullptr);

    // layers 1..3 (residual)
    for (int i = 0; i < 3; i++) {
        dim3 ng((NN + 127) / 128, 2);
        gemm_node<<<ng, 256, NODE_SMEM>>>(Wl + i * HID * HID, bl + i * HID,
                                          Wr + i * HID * HID, br + i * HID);
        wprep_kernel<<<32, 256>>>(We + i * HID * HID);
        gemm_edge_score_mma<<<EE / 128, 512, ESM_BYTES>>>(att + i * HID, ei);
        if (i < 2)
            node_fused_kernel<true, false><<<NN / 4, 128>>>(
                ei, bias + i * HID, lng + (i + 1) * HID, lnb + (i + 1) * HID, nullptr);
        else
            node_fused_kernel<true, true><<<NN / 4, 128>>>(
                ei, bias + i * HID, lng + (i + 1) * HID, lnb + (i + 1) * HID, out);
    }
}